// round 1
// baseline (speedup 1.0000x reference)
#include <cuda_runtime.h>
#include <cuda_bf16.h>

#define BQ  16
#define HH  512
#define WW  512
#define MM  64
#define NPTS 5
#define NTOT (BQ*HH*WW)      // 4194304
#define NBLK 1024
#define NTHR 256

// Scratch (no allocation allowed): partial sums + per-batch box results.
__device__ float g_part[NBLK*4];   // [block][bce, p*t, p, t]
__device__ float g_box[BQ*3];      // [b][combined, conf, valid]

__device__ __forceinline__ float wredf(float v){
  #pragma unroll
  for (int o = 16; o > 0; o >>= 1) v += __shfl_xor_sync(0xffffffffu, v, o);
  return v;
}
__device__ __forceinline__ double wredd(double v){
  #pragma unroll
  for (int o = 16; o > 0; o >>= 1) v += __shfl_xor_sync(0xffffffffu, v, o);
  return v;
}
__device__ __forceinline__ float clipf(float x, float lo, float hi){
  return fminf(fmaxf(x, lo), hi);
}
__device__ __forceinline__ float sl1(float d){
  d = fabsf(d);
  return (d < 1.0f) ? 0.5f*d*d : d - 0.5f;
}

// ---------------- Kernel 1: text map BCE + dice sums (HBM-bound) -------------
__global__ void __launch_bounds__(NTHR)
text_kernel(const float4* __restrict__ p4, const float4* __restrict__ t4){
  int idx = blockIdx.x * NTHR + threadIdx.x;
  float sb = 0.f, spt = 0.f, sp = 0.f, st = 0.f;
  const int n4 = NTOT / 4;
  for (int i = idx; i < n4; i += NBLK*NTHR){
    float4 pv = p4[i];
    float4 tv = t4[i];
    float pa[4] = {pv.x, pv.y, pv.z, pv.w};
    float ta[4] = {tv.x, tv.y, tv.z, tv.w};
    #pragma unroll
    for (int c = 0; c < 4; c++){
      float pp = pa[c], tt = ta[c];
      // t is exactly 0 or 1: bce = -log(p) if t==1 else -log(1-p)
      sb  -= __logf(tt > 0.5f ? pp : 1.0f - pp);
      spt  = fmaf(pp, tt, spt);
      sp  += pp;
      st  += tt;
    }
  }
  sb  = wredf(sb);  spt = wredf(spt);
  sp  = wredf(sp);  st  = wredf(st);
  __shared__ float sh[4][NTHR/32];
  int w = threadIdx.x >> 5, l = threadIdx.x & 31;
  if (l == 0){ sh[0][w] = sb; sh[1][w] = spt; sh[2][w] = sp; sh[3][w] = st; }
  __syncthreads();
  if (threadIdx.x == 0){
    float a = 0.f, b = 0.f, c = 0.f, d = 0.f;
    #pragma unroll
    for (int i = 0; i < NTHR/32; i++){ a += sh[0][i]; b += sh[1][i]; c += sh[2][i]; d += sh[3][i]; }
    g_part[blockIdx.x*4+0] = a;
    g_part[blockIdx.x*4+1] = b;
    g_part[blockIdx.x*4+2] = c;
    g_part[blockIdx.x*4+3] = d;
  }
}

// ---------------- Kernel 2: box/conf losses (sparse gather, tiny) ------------
__global__ void __launch_bounds__(MM*NPTS)
box_kernel(const float* __restrict__ bbox,      // [B,4,H,W]
           const float* __restrict__ conf,      // [B,1,H,W]
           const float* __restrict__ tboxes,    // [B,M,5]
           const int*   __restrict__ bmask){    // [B,M]
  int b   = blockIdx.x;
  int tid = threadIdx.x;                        // 0..319
  int m   = tid / NPTS;
  int pt  = tid % NPTS;

  const float* tbm = tboxes + ((size_t)b*MM + m)*5;
  float tconf = tbm[0];
  // /512 is exact (power of 2); truncation matches astype(int32)
  float nx1 = clipf(tbm[1] * (1.0f/512.0f), 0.f, 1.f);
  float ny1 = clipf(tbm[2] * (1.0f/512.0f), 0.f, 1.f);
  float nx2 = clipf(tbm[3] * (1.0f/512.0f), 0.f, 1.f);
  float ny2 = clipf(tbm[4] * (1.0f/512.0f), 0.f, 1.f);
  int x1p = min(max((int)(nx1 * 512.0f), 0), WW-1);
  int y1p = min(max((int)(ny1 * 512.0f), 0), HH-1);
  int x2p = min(max((int)(nx2 * 512.0f), 0), WW-1);
  int y2p = min(max((int)(ny2 * 512.0f), 0), HH-1);
  int cy = (y1p + y2p) >> 1;
  int cx = (x1p + x2p) >> 1;

  int yy, xx;
  switch (pt){
    case 0: yy = cy;  xx = cx;  break;
    case 1: yy = y1p; xx = x1p; break;
    case 2: yy = y1p; xx = x2p; break;
    case 3: yy = y2p; xx = x1p; break;
    default:yy = y2p; xx = x2p; break;
  }

  size_t hw  = (size_t)HH*WW;
  size_t off = (size_t)yy*WW + xx;
  const float* bb = bbox + (size_t)b*4*hw;
  float c0 = bb[off];
  float c1 = bb[hw   + off];
  float c2 = bb[2*hw + off];
  float c3 = bb[3*hw + off];
  float cp = conf[(size_t)b*hw + off];

  float px1 = clipf(c0, 0.00f, 0.99f);
  float py1 = clipf(c1, 0.00f, 0.99f);
  float px2 = clipf(c2, 0.01f, 1.00f);
  float py2 = clipf(c3, 0.01f, 1.00f);
  float bx1 = fminf(px1, px2), bx2 = fmaxf(px1, px2);
  float by1 = fminf(py1, py2), by2 = fmaxf(py1, py2);

  float pa = (bx2 - bx1) * (by2 - by1);
  float ta = (nx2 - nx1) * (ny2 - ny1);
  float ix1 = fmaxf(bx1, nx1), iy1 = fmaxf(by1, ny1);
  float ix2 = fminf(bx2, nx2), iy2 = fminf(by2, ny2);
  float inter = fmaxf(ix2 - ix1, 0.f) * fmaxf(iy2 - iy1, 0.f);
  float uni = pa + ta - inter;
  float iou = inter / (uni + 1e-6f);
  float ex1 = fminf(bx1, nx1), ey1 = fminf(by1, ny1);
  float ex2 = fmaxf(bx2, nx2), ey2 = fmaxf(by2, ny2);
  float enc = (ex2 - ex1) * (ey2 - ey1);
  float giou = iou - (enc - uni) / (enc + 1e-6f);

  float iou_pt  = -__logf(iou + 1e-6f);
  float giou_pt = 1.0f - giou;
  float l1_pt   = 0.25f * (sl1(bx1-nx1) + sl1(by1-ny1) + sl1(bx2-nx2) + sl1(by2-ny2));
  float bce     = -(tconf*__logf(cp) + (1.0f - tconf)*__logf(1.0f - cp));

  float mk = (float)bmask[b*MM + m];

  float s0 = iou_pt  * mk;
  float s1 = l1_pt   * mk;
  float s2 = giou_pt * mk;
  float s3 = bce     * mk;
  float s4 = mk;

  s0 = wredf(s0); s1 = wredf(s1); s2 = wredf(s2); s3 = wredf(s3); s4 = wredf(s4);
  __shared__ float sh[5][(MM*NPTS)/32];      // 10 warps
  int w = tid >> 5, l = tid & 31;
  if (l == 0){ sh[0][w]=s0; sh[1][w]=s1; sh[2][w]=s2; sh[3][w]=s3; sh[4][w]=s4; }
  __syncthreads();
  if (tid == 0){
    float a0=0,a1=0,a2=0,a3=0,a4=0;
    #pragma unroll
    for (int i = 0; i < (MM*NPTS)/32; i++){
      a0+=sh[0][i]; a1+=sh[1][i]; a2+=sh[2][i]; a3+=sh[3][i]; a4+=sh[4][i];
    }
    float cnt = fmaxf(a4, 1.0f);
    float combined = 0.5f*(a0/cnt) + 0.3f*(a1/cnt) + 0.2f*(a2/cnt);
    float confl    = a3/cnt;
    float valid    = (a4 > 0.f) ? 1.0f : 0.0f;
    g_box[b*3+0] = combined;
    g_box[b*3+1] = confl;
    g_box[b*3+2] = valid;
  }
}

// ---------------- Kernel 3: final combine (1 block) --------------------------
__global__ void __launch_bounds__(256)
final_kernel(float* __restrict__ out){
  int tid = threadIdx.x;
  double s0=0.0, s1=0.0, s2=0.0, s3=0.0;
  for (int i = tid; i < NBLK; i += 256){
    s0 += (double)g_part[i*4+0];
    s1 += (double)g_part[i*4+1];
    s2 += (double)g_part[i*4+2];
    s3 += (double)g_part[i*4+3];
  }
  s0 = wredd(s0); s1 = wredd(s1); s2 = wredd(s2); s3 = wredd(s3);
  __shared__ double sh[4][8];
  int w = tid >> 5, l = tid & 31;
  if (l == 0){ sh[0][w]=s0; sh[1][w]=s1; sh[2][w]=s2; sh[3][w]=s3; }
  __syncthreads();
  if (tid == 0){
    double Sb=0, Spt=0, Sp=0, St=0;
    #pragma unroll
    for (int i = 0; i < 8; i++){ Sb+=sh[0][i]; Spt+=sh[1][i]; Sp+=sh[2][i]; St+=sh[3][i]; }
    float bce_mean = (float)(Sb / (double)NTOT);
    float dice = (float)((2.0*Spt + 1e-5) / (Sp + St + 1e-5));
    float text_loss = 0.5f*bce_mean + 0.5f*(1.0f - dice);

    float nvalid = 0.f, sc = 0.f, scf = 0.f;
    #pragma unroll
    for (int b = 0; b < BQ; b++){
      float v = g_box[b*3+2];
      nvalid += v;
      sc  += g_box[b*3+0] * v;
      scf += g_box[b*3+1] * v;
    }
    nvalid = fmaxf(nvalid, 1.0f);
    float box_loss  = sc  / nvalid;
    float conf_loss = scf / nvalid;
    out[0] = text_loss + 20.0f*box_loss + 0.5f*conf_loss;
  }
}

extern "C" void kernel_launch(void* const* d_in, const int* in_sizes, int n_in,
                              void* d_out, int out_size){
  const float* text_map        = (const float*)d_in[0];
  const float* confidence      = (const float*)d_in[1];
  const float* bbox_coords     = (const float*)d_in[2];
  const float* target_text_map = (const float*)d_in[3];
  const float* target_boxes    = (const float*)d_in[4];
  const int*   box_mask        = (const int*)  d_in[5];
  float* out = (float*)d_out;

  text_kernel<<<NBLK, NTHR>>>((const float4*)text_map, (const float4*)target_text_map);
  box_kernel<<<BQ, MM*NPTS>>>(bbox_coords, confidence, target_boxes, box_mask);
  final_kernel<<<1, 256>>>(out);
}

// round 2
// speedup vs baseline: 1.0169x; 1.0169x over previous
#include <cuda_runtime.h>
#include <cuda_bf16.h>

#define BQ  16
#define HH  512
#define WW  512
#define MM  64
#define NPTS 5
#define NTOT (BQ*HH*WW)      // 4194304
#define NBLK 1024
#define NTHR 256
#define GRID (NBLK + BQ)

// Scratch (no allocation allowed)
__device__ float g_part[NBLK*4];        // [block][bce, p*t, p, t]
__device__ float g_box[BQ*3];           // [b][combined, conf, valid]
__device__ unsigned int g_count;        // zero-initialized at module load

__device__ __forceinline__ float wredf(float v){
  #pragma unroll
  for (int o = 16; o > 0; o >>= 1) v += __shfl_xor_sync(0xffffffffu, v, o);
  return v;
}
__device__ __forceinline__ double wredd(double v){
  #pragma unroll
  for (int o = 16; o > 0; o >>= 1) v += __shfl_xor_sync(0xffffffffu, v, o);
  return v;
}
__device__ __forceinline__ float clipf(float x, float lo, float hi){
  return fminf(fmaxf(x, lo), hi);
}
__device__ __forceinline__ float sl1(float d){
  d = fabsf(d);
  return (d < 1.0f) ? 0.5f*d*d : d - 0.5f;
}

__global__ void __launch_bounds__(NTHR)
fused_kernel(const float4* __restrict__ p4,        // text_map
             const float4* __restrict__ t4,        // target_text_map
             const float*  __restrict__ bbox,      // [B,4,H,W]
             const float*  __restrict__ conf,      // [B,1,H,W]
             const float*  __restrict__ tboxes,    // [B,M,5]
             const int*    __restrict__ bmask,     // [B,M]
             float*        __restrict__ out){
  const int tid = threadIdx.x;
  const int w = tid >> 5, l = tid & 31;

  if (blockIdx.x < NBLK){
    // ---------------- text map BCE + dice partial sums (HBM-bound) ----------
    const int base   = blockIdx.x * NTHR + tid;
    const int stride = NBLK * NTHR;          // 262144; n4 = 1048576 = 4*stride
    float4 pv[4], tv[4];
    #pragma unroll
    for (int k = 0; k < 4; k++) pv[k] = p4[base + k*stride];
    #pragma unroll
    for (int k = 0; k < 4; k++) tv[k] = t4[base + k*stride];

    float sb = 0.f, spt = 0.f, sp = 0.f, st = 0.f;
    #pragma unroll
    for (int k = 0; k < 4; k++){
      float pa[4] = {pv[k].x, pv[k].y, pv[k].z, pv[k].w};
      float ta[4] = {tv[k].x, tv[k].y, tv[k].z, tv[k].w};
      #pragma unroll
      for (int c = 0; c < 4; c++){
        float pp = pa[c], tt = ta[c];
        // t is exactly 0 or 1
        sb  -= __logf(tt > 0.5f ? pp : 1.0f - pp);
        spt  = fmaf(pp, tt, spt);
        sp  += pp;
        st  += tt;
      }
    }
    sb = wredf(sb); spt = wredf(spt); sp = wredf(sp); st = wredf(st);
    __shared__ float sh[4][NTHR/32];
    if (l == 0){ sh[0][w]=sb; sh[1][w]=spt; sh[2][w]=sp; sh[3][w]=st; }
    __syncthreads();
    if (tid == 0){
      float a=0.f,b=0.f,c=0.f,d=0.f;
      #pragma unroll
      for (int i = 0; i < NTHR/32; i++){ a+=sh[0][i]; b+=sh[1][i]; c+=sh[2][i]; d+=sh[3][i]; }
      g_part[blockIdx.x*4+0]=a; g_part[blockIdx.x*4+1]=b;
      g_part[blockIdx.x*4+2]=c; g_part[blockIdx.x*4+3]=d;
    }
  } else {
    // ---------------- box/conf losses for batch b (tiny) --------------------
    const int b = blockIdx.x - NBLK;
    float s0=0.f, s1=0.f, s2=0.f, s3=0.f, s4=0.f;
    for (int i = tid; i < MM*NPTS; i += NTHR){
      int m  = i / NPTS;
      int pt = i % NPTS;
      const float* tbm = tboxes + ((size_t)b*MM + m)*5;
      float tconf = tbm[0];
      float nx1 = clipf(tbm[1] * (1.0f/512.0f), 0.f, 1.f);
      float ny1 = clipf(tbm[2] * (1.0f/512.0f), 0.f, 1.f);
      float nx2 = clipf(tbm[3] * (1.0f/512.0f), 0.f, 1.f);
      float ny2 = clipf(tbm[4] * (1.0f/512.0f), 0.f, 1.f);
      int x1p = min(max((int)(nx1 * 512.0f), 0), WW-1);
      int y1p = min(max((int)(ny1 * 512.0f), 0), HH-1);
      int x2p = min(max((int)(nx2 * 512.0f), 0), WW-1);
      int y2p = min(max((int)(ny2 * 512.0f), 0), HH-1);
      int cy = (y1p + y2p) >> 1;
      int cx = (x1p + x2p) >> 1;

      int yy, xx;
      switch (pt){
        case 0: yy = cy;  xx = cx;  break;
        case 1: yy = y1p; xx = x1p; break;
        case 2: yy = y1p; xx = x2p; break;
        case 3: yy = y2p; xx = x1p; break;
        default:yy = y2p; xx = x2p; break;
      }

      size_t hw  = (size_t)HH*WW;
      size_t off = (size_t)yy*WW + xx;
      const float* bb = bbox + (size_t)b*4*hw;
      float c0 = bb[off];
      float c1 = bb[hw   + off];
      float c2 = bb[2*hw + off];
      float c3 = bb[3*hw + off];
      float cp = conf[(size_t)b*hw + off];

      float px1 = clipf(c0, 0.00f, 0.99f);
      float py1 = clipf(c1, 0.00f, 0.99f);
      float px2 = clipf(c2, 0.01f, 1.00f);
      float py2 = clipf(c3, 0.01f, 1.00f);
      float bx1 = fminf(px1, px2), bx2 = fmaxf(px1, px2);
      float by1 = fminf(py1, py2), by2 = fmaxf(py1, py2);

      float pa = (bx2 - bx1) * (by2 - by1);
      float ta = (nx2 - nx1) * (ny2 - ny1);
      float ix1 = fmaxf(bx1, nx1), iy1 = fmaxf(by1, ny1);
      float ix2 = fminf(bx2, nx2), iy2 = fminf(by2, ny2);
      float inter = fmaxf(ix2 - ix1, 0.f) * fmaxf(iy2 - iy1, 0.f);
      float uni = pa + ta - inter;
      float iou = inter / (uni + 1e-6f);
      float ex1 = fminf(bx1, nx1), ey1 = fminf(by1, ny1);
      float ex2 = fmaxf(bx2, nx2), ey2 = fmaxf(by2, ny2);
      float enc = (ex2 - ex1) * (ey2 - ey1);
      float giou = iou - (enc - uni) / (enc + 1e-6f);

      float iou_pt  = -__logf(iou + 1e-6f);
      float giou_pt = 1.0f - giou;
      float l1_pt   = 0.25f * (sl1(bx1-nx1) + sl1(by1-ny1) + sl1(bx2-nx2) + sl1(by2-ny2));
      float bce     = -(tconf*__logf(cp) + (1.0f - tconf)*__logf(1.0f - cp));

      float mk = (float)bmask[b*MM + m];
      s0 = fmaf(iou_pt,  mk, s0);
      s1 = fmaf(l1_pt,   mk, s1);
      s2 = fmaf(giou_pt, mk, s2);
      s3 = fmaf(bce,     mk, s3);
      s4 += mk;
    }
    s0 = wredf(s0); s1 = wredf(s1); s2 = wredf(s2); s3 = wredf(s3); s4 = wredf(s4);
    __shared__ float shb[5][NTHR/32];
    if (l == 0){ shb[0][w]=s0; shb[1][w]=s1; shb[2][w]=s2; shb[3][w]=s3; shb[4][w]=s4; }
    __syncthreads();
    if (tid == 0){
      float a0=0,a1=0,a2=0,a3=0,a4=0;
      #pragma unroll
      for (int i = 0; i < NTHR/32; i++){
        a0+=shb[0][i]; a1+=shb[1][i]; a2+=shb[2][i]; a3+=shb[3][i]; a4+=shb[4][i];
      }
      float cnt = fmaxf(a4, 1.0f);
      g_box[b*3+0] = 0.5f*(a0/cnt) + 0.3f*(a1/cnt) + 0.2f*(a2/cnt);
      g_box[b*3+1] = a3/cnt;
      g_box[b*3+2] = (a4 > 0.f) ? 1.0f : 0.0f;
    }
  }

  // ---------------- last block finishes (deterministic combine) -------------
  __threadfence();
  __shared__ bool isLast;
  if (tid == 0){
    unsigned int v = atomicAdd(&g_count, 1u);
    isLast = (v == (unsigned int)(GRID - 1));
  }
  __syncthreads();
  if (!isLast) return;

  double s0=0.0, s1=0.0, s2=0.0, s3=0.0;
  for (int i = tid; i < NBLK; i += NTHR){
    s0 += (double)g_part[i*4+0];
    s1 += (double)g_part[i*4+1];
    s2 += (double)g_part[i*4+2];
    s3 += (double)g_part[i*4+3];
  }
  s0 = wredd(s0); s1 = wredd(s1); s2 = wredd(s2); s3 = wredd(s3);
  __shared__ double shd[4][NTHR/32];
  if (l == 0){ shd[0][w]=s0; shd[1][w]=s1; shd[2][w]=s2; shd[3][w]=s3; }
  __syncthreads();
  if (tid == 0){
    double Sb=0, Spt=0, Sp=0, St=0;
    #pragma unroll
    for (int i = 0; i < NTHR/32; i++){ Sb+=shd[0][i]; Spt+=shd[1][i]; Sp+=shd[2][i]; St+=shd[3][i]; }
    float bce_mean = (float)(Sb / (double)NTOT);
    float dice = (float)((2.0*Spt + 1e-5) / (Sp + St + 1e-5));
    float text_loss = 0.5f*bce_mean + 0.5f*(1.0f - dice);

    float nvalid = 0.f, sc = 0.f, scf = 0.f;
    #pragma unroll
    for (int b = 0; b < BQ; b++){
      float v = g_box[b*3+2];
      nvalid += v;
      sc  += g_box[b*3+0] * v;
      scf += g_box[b*3+1] * v;
    }
    nvalid = fmaxf(nvalid, 1.0f);
    out[0] = text_loss + 20.0f*(sc/nvalid) + 0.5f*(scf/nvalid);
    g_count = 0;   // reset for next graph replay
  }
}

extern "C" void kernel_launch(void* const* d_in, const int* in_sizes, int n_in,
                              void* d_out, int out_size){
  const float* text_map        = (const float*)d_in[0];
  const float* confidence      = (const float*)d_in[1];
  const float* bbox_coords     = (const float*)d_in[2];
  const float* target_text_map = (const float*)d_in[3];
  const float* target_boxes    = (const float*)d_in[4];
  const int*   box_mask        = (const int*)  d_in[5];

  fused_kernel<<<GRID, NTHR>>>((const float4*)text_map, (const float4*)target_text_map,
                               bbox_coords, confidence, target_boxes, box_mask,
                               (float*)d_out);
}

// round 3
// speedup vs baseline: 1.1199x; 1.1014x over previous
#include <cuda_runtime.h>
#include <cuda_bf16.h>

#define BQ  16
#define HH  512
#define WW  512
#define MM  64
#define NPTS 5
#define NTOT (BQ*HH*WW)      // 4194304
#define NBLK 1024
#define NTHR 256
#define GRID (NBLK + BQ)

// Scratch (no allocation allowed)
__device__ float g_part[NBLK*4];        // [block][bce, p*t, p, t]
__device__ float g_box[BQ*3];           // [b][combined, conf, valid]
__device__ unsigned int g_count;        // zero-initialized at module load

__device__ __forceinline__ float wredf(float v){
  #pragma unroll
  for (int o = 16; o > 0; o >>= 1) v += __shfl_xor_sync(0xffffffffu, v, o);
  return v;
}
__device__ __forceinline__ double wredd(double v){
  #pragma unroll
  for (int o = 16; o > 0; o >>= 1) v += __shfl_xor_sync(0xffffffffu, v, o);
  return v;
}
__device__ __forceinline__ float clipf(float x, float lo, float hi){
  return fminf(fmaxf(x, lo), hi);
}
__device__ __forceinline__ float sl1(float d){
  d = fabsf(d);
  return (d < 1.0f) ? 0.5f*d*d : d - 0.5f;
}

__device__ __forceinline__ void acc4(float4 pv, float4 tv,
                                     float& sb, float& spt, float& sp, float& st){
  float pa[4] = {pv.x, pv.y, pv.z, pv.w};
  float ta[4] = {tv.x, tv.y, tv.z, tv.w};
  #pragma unroll
  for (int c = 0; c < 4; c++){
    float pp = pa[c], tt = ta[c];
    // t is exactly 0 or 1
    sb  -= __logf(tt > 0.5f ? pp : 1.0f - pp);
    spt  = fmaf(pp, tt, spt);
    sp  += pp;
    st  += tt;
  }
}

__global__ void __launch_bounds__(NTHR)
fused_kernel(const float4* __restrict__ p4,        // text_map
             const float4* __restrict__ t4,        // target_text_map
             const float*  __restrict__ bbox,      // [B,4,H,W]
             const float*  __restrict__ conf,      // [B,1,H,W]
             const float*  __restrict__ tboxes,    // [B,M,5]
             const int*    __restrict__ bmask,     // [B,M]
             float*        __restrict__ out){
  const int tid = threadIdx.x;
  const int w = tid >> 5, l = tid & 31;

  if (blockIdx.x < NBLK){
    // ---------------- text map BCE + dice partial sums (HBM-bound) ----------
    const int base = blockIdx.x * NTHR + tid;
    const int S    = NBLK * NTHR;            // 262144; n4 = 4*S
    float sb = 0.f, spt = 0.f, sp = 0.f, st = 0.f;
    // Two iterations, each with 4 independent 16B loads in flight (MLP=4).
    #pragma unroll 1
    for (int k = 0; k < 2; k++){
      int i0 = base + (2*k  )*S;
      int i1 = base + (2*k+1)*S;
      float4 a0 = p4[i0];
      float4 b0 = t4[i0];
      float4 a1 = p4[i1];
      float4 b1 = t4[i1];
      acc4(a0, b0, sb, spt, sp, st);
      acc4(a1, b1, sb, spt, sp, st);
    }
    sb = wredf(sb); spt = wredf(spt); sp = wredf(sp); st = wredf(st);
    __shared__ float sh[4][NTHR/32];
    if (l == 0){ sh[0][w]=sb; sh[1][w]=spt; sh[2][w]=sp; sh[3][w]=st; }
    __syncthreads();
    if (tid == 0){
      float a=0.f,b=0.f,c=0.f,d=0.f;
      #pragma unroll
      for (int i = 0; i < NTHR/32; i++){ a+=sh[0][i]; b+=sh[1][i]; c+=sh[2][i]; d+=sh[3][i]; }
      g_part[blockIdx.x*4+0]=a; g_part[blockIdx.x*4+1]=b;
      g_part[blockIdx.x*4+2]=c; g_part[blockIdx.x*4+3]=d;
    }
  } else {
    // ---------------- box/conf losses for batch b (tiny) --------------------
    const int b = blockIdx.x - NBLK;
    float s0=0.f, s1=0.f, s2=0.f, s3=0.f, s4=0.f;
    for (int i = tid; i < MM*NPTS; i += NTHR){
      int m  = i / NPTS;
      int pt = i % NPTS;
      const float* tbm = tboxes + ((size_t)b*MM + m)*5;
      float tconf = tbm[0];
      float nx1 = clipf(tbm[1] * (1.0f/512.0f), 0.f, 1.f);
      float ny1 = clipf(tbm[2] * (1.0f/512.0f), 0.f, 1.f);
      float nx2 = clipf(tbm[3] * (1.0f/512.0f), 0.f, 1.f);
      float ny2 = clipf(tbm[4] * (1.0f/512.0f), 0.f, 1.f);
      int x1p = min(max((int)(nx1 * 512.0f), 0), WW-1);
      int y1p = min(max((int)(ny1 * 512.0f), 0), HH-1);
      int x2p = min(max((int)(nx2 * 512.0f), 0), WW-1);
      int y2p = min(max((int)(ny2 * 512.0f), 0), HH-1);
      int cy = (y1p + y2p) >> 1;
      int cx = (x1p + x2p) >> 1;

      int yy, xx;
      switch (pt){
        case 0: yy = cy;  xx = cx;  break;
        case 1: yy = y1p; xx = x1p; break;
        case 2: yy = y1p; xx = x2p; break;
        case 3: yy = y2p; xx = x1p; break;
        default:yy = y2p; xx = x2p; break;
      }

      size_t hw  = (size_t)HH*WW;
      size_t off = (size_t)yy*WW + xx;
      const float* bb = bbox + (size_t)b*4*hw;
      float c0 = bb[off];
      float c1 = bb[hw   + off];
      float c2 = bb[2*hw + off];
      float c3 = bb[3*hw + off];
      float cp = conf[(size_t)b*hw + off];

      float px1 = clipf(c0, 0.00f, 0.99f);
      float py1 = clipf(c1, 0.00f, 0.99f);
      float px2 = clipf(c2, 0.01f, 1.00f);
      float py2 = clipf(c3, 0.01f, 1.00f);
      float bx1 = fminf(px1, px2), bx2 = fmaxf(px1, px2);
      float by1 = fminf(py1, py2), by2 = fmaxf(py1, py2);

      float pa = (bx2 - bx1) * (by2 - by1);
      float ta = (nx2 - nx1) * (ny2 - ny1);
      float ix1 = fmaxf(bx1, nx1), iy1 = fmaxf(by1, ny1);
      float ix2 = fminf(bx2, nx2), iy2 = fminf(by2, ny2);
      float inter = fmaxf(ix2 - ix1, 0.f) * fmaxf(iy2 - iy1, 0.f);
      float uni = pa + ta - inter;
      float iou = inter / (uni + 1e-6f);
      float ex1 = fminf(bx1, nx1), ey1 = fminf(by1, ny1);
      float ex2 = fmaxf(bx2, nx2), ey2 = fmaxf(by2, ny2);
      float enc = (ex2 - ex1) * (ey2 - ey1);
      float giou = iou - (enc - uni) / (enc + 1e-6f);

      float iou_pt  = -__logf(iou + 1e-6f);
      float giou_pt = 1.0f - giou;
      float l1_pt   = 0.25f * (sl1(bx1-nx1) + sl1(by1-ny1) + sl1(bx2-nx2) + sl1(by2-ny2));
      float bce     = -(tconf*__logf(cp) + (1.0f - tconf)*__logf(1.0f - cp));

      float mk = (float)bmask[b*MM + m];
      s0 = fmaf(iou_pt,  mk, s0);
      s1 = fmaf(l1_pt,   mk, s1);
      s2 = fmaf(giou_pt, mk, s2);
      s3 = fmaf(bce,     mk, s3);
      s4 += mk;
    }
    s0 = wredf(s0); s1 = wredf(s1); s2 = wredf(s2); s3 = wredf(s3); s4 = wredf(s4);
    __shared__ float shb[5][NTHR/32];
    if (l == 0){ shb[0][w]=s0; shb[1][w]=s1; shb[2][w]=s2; shb[3][w]=s3; shb[4][w]=s4; }
    __syncthreads();
    if (tid == 0){
      float a0=0,a1=0,a2=0,a3=0,a4=0;
      #pragma unroll
      for (int i = 0; i < NTHR/32; i++){
        a0+=shb[0][i]; a1+=shb[1][i]; a2+=shb[2][i]; a3+=shb[3][i]; a4+=shb[4][i];
      }
      float cnt = fmaxf(a4, 1.0f);
      g_box[b*3+0] = 0.5f*(a0/cnt) + 0.3f*(a1/cnt) + 0.2f*(a2/cnt);
      g_box[b*3+1] = a3/cnt;
      g_box[b*3+2] = (a4 > 0.f) ? 1.0f : 0.0f;
    }
  }

  // ------- last-block combine. ONLY tid 0 fences + bumps the counter -------
  __shared__ bool isLast;
  if (tid == 0){
    __threadfence();                       // release g_part/g_box (written by tid 0)
    unsigned int v = atomicAdd(&g_count, 1u);
    isLast = (v == (unsigned int)(GRID - 1));
    if (isLast) __threadfence();           // acquire before reading others' results
  }
  __syncthreads();
  if (!isLast) return;

  double s0=0.0, s1=0.0, s2=0.0, s3=0.0;
  for (int i = tid; i < NBLK; i += NTHR){
    s0 += (double)g_part[i*4+0];
    s1 += (double)g_part[i*4+1];
    s2 += (double)g_part[i*4+2];
    s3 += (double)g_part[i*4+3];
  }
  s0 = wredd(s0); s1 = wredd(s1); s2 = wredd(s2); s3 = wredd(s3);
  __shared__ double shd[4][NTHR/32];
  if (l == 0){ shd[0][w]=s0; shd[1][w]=s1; shd[2][w]=s2; shd[3][w]=s3; }
  __syncthreads();
  if (tid == 0){
    double Sb=0, Spt=0, Sp=0, St=0;
    #pragma unroll
    for (int i = 0; i < NTHR/32; i++){ Sb+=shd[0][i]; Spt+=shd[1][i]; Sp+=shd[2][i]; St+=shd[3][i]; }
    float bce_mean = (float)(Sb / (double)NTOT);
    float dice = (float)((2.0*Spt + 1e-5) / (Sp + St + 1e-5));
    float text_loss = 0.5f*bce_mean + 0.5f*(1.0f - dice);

    float nvalid = 0.f, sc = 0.f, scf = 0.f;
    #pragma unroll
    for (int b = 0; b < BQ; b++){
      float v = g_box[b*3+2];
      nvalid += v;
      sc  += g_box[b*3+0] * v;
      scf += g_box[b*3+1] * v;
    }
    nvalid = fmaxf(nvalid, 1.0f);
    out[0] = text_loss + 20.0f*(sc/nvalid) + 0.5f*(scf/nvalid);
    g_count = 0;   // reset for next graph replay
  }
}

extern "C" void kernel_launch(void* const* d_in, const int* in_sizes, int n_in,
                              void* d_out, int out_size){
  const float* text_map        = (const float*)d_in[0];
  const float* confidence      = (const float*)d_in[1];
  const float* bbox_coords     = (const float*)d_in[2];
  const float* target_text_map = (const float*)d_in[3];
  const float* target_boxes    = (const float*)d_in[4];
  const int*   box_mask        = (const int*)  d_in[5];

  fused_kernel<<<GRID, NTHR>>>((const float4*)text_map, (const float4*)target_text_map,
                               bbox_coords, confidence, target_boxes, box_mask,
                               (float*)d_out);
}

// round 4
// speedup vs baseline: 1.1218x; 1.0017x over previous
#include <cuda_runtime.h>
#include <cuda_bf16.h>

#define BQ  16
#define HH  512
#define WW  512
#define MM  64
#define NPTS 5
#define NTOT (BQ*HH*WW)      // 4194304
#define NBLK 1024
#define NTHR 256
#define GRID (NBLK + BQ)

// Scratch (no allocation allowed)
__device__ float g_part[NBLK*4];        // [block][bce, p*t, p, t]
__device__ float g_box[BQ*3];           // [b][combined, conf, valid]
__device__ unsigned int g_count;        // zero-initialized at module load

__device__ __forceinline__ float wredf(float v){
  #pragma unroll
  for (int o = 16; o > 0; o >>= 1) v += __shfl_xor_sync(0xffffffffu, v, o);
  return v;
}
__device__ __forceinline__ double wredd(double v){
  #pragma unroll
  for (int o = 16; o > 0; o >>= 1) v += __shfl_xor_sync(0xffffffffu, v, o);
  return v;
}
__device__ __forceinline__ float clipf(float x, float lo, float hi){
  return fminf(fmaxf(x, lo), hi);
}
__device__ __forceinline__ float sl1(float d){
  d = fabsf(d);
  return (d < 1.0f) ? 0.5f*d*d : d - 0.5f;
}

// Pinned vector load: volatile asm cannot be reordered, guaranteeing the
// 8 loads per thread are issued back-to-back (MLP=8) before any compute.
__device__ __forceinline__ float4 ldg4(const float4* p){
  float4 v;
  asm volatile("ld.global.nc.v4.f32 {%0,%1,%2,%3}, [%4];"
               : "=f"(v.x), "=f"(v.y), "=f"(v.z), "=f"(v.w) : "l"(p));
  return v;
}

__device__ __forceinline__ void acc4(float4 pv, float4 tv,
                                     float& sb, float& spt, float& sp, float& st){
  float pa[4] = {pv.x, pv.y, pv.z, pv.w};
  float ta[4] = {tv.x, tv.y, tv.z, tv.w};
  #pragma unroll
  for (int c = 0; c < 4; c++){
    float pp = pa[c], tt = ta[c];
    // t is exactly 0 or 1
    sb  -= __logf(tt > 0.5f ? pp : 1.0f - pp);
    spt  = fmaf(pp, tt, spt);
    sp  += pp;
    st  += tt;
  }
}

__global__ void __launch_bounds__(NTHR)
fused_kernel(const float4* __restrict__ p4,        // text_map
             const float4* __restrict__ t4,        // target_text_map
             const float*  __restrict__ bbox,      // [B,4,H,W]
             const float*  __restrict__ conf,      // [B,1,H,W]
             const float*  __restrict__ tboxes,    // [B,M,5]
             const int*    __restrict__ bmask,     // [B,M]
             float*        __restrict__ out){
  const int tid = threadIdx.x;
  const int w = tid >> 5, l = tid & 31;

  if (blockIdx.x < NBLK){
    // ------------- text map BCE + dice partial sums (HBM-bound) -------------
    const int base = blockIdx.x * NTHR + tid;
    const int S    = NBLK * NTHR;            // 262144; n4 = 4*S

    // All 8 loads issued before any compute (forced by volatile asm).
    float4 pv0 = ldg4(p4 + base      );
    float4 pv1 = ldg4(p4 + base +   S);
    float4 pv2 = ldg4(p4 + base + 2*S);
    float4 pv3 = ldg4(p4 + base + 3*S);
    float4 tv0 = ldg4(t4 + base      );
    float4 tv1 = ldg4(t4 + base +   S);
    float4 tv2 = ldg4(t4 + base + 2*S);
    float4 tv3 = ldg4(t4 + base + 3*S);

    float sb = 0.f, spt = 0.f, sp = 0.f, st = 0.f;
    acc4(pv0, tv0, sb, spt, sp, st);
    acc4(pv1, tv1, sb, spt, sp, st);
    acc4(pv2, tv2, sb, spt, sp, st);
    acc4(pv3, tv3, sb, spt, sp, st);

    sb = wredf(sb); spt = wredf(spt); sp = wredf(sp); st = wredf(st);
    __shared__ float sh[4][NTHR/32];
    if (l == 0){ sh[0][w]=sb; sh[1][w]=spt; sh[2][w]=sp; sh[3][w]=st; }
    __syncthreads();
    if (tid == 0){
      float a=0.f,b=0.f,c=0.f,d=0.f;
      #pragma unroll
      for (int i = 0; i < NTHR/32; i++){ a+=sh[0][i]; b+=sh[1][i]; c+=sh[2][i]; d+=sh[3][i]; }
      g_part[blockIdx.x*4+0]=a; g_part[blockIdx.x*4+1]=b;
      g_part[blockIdx.x*4+2]=c; g_part[blockIdx.x*4+3]=d;
    }
  } else {
    // ---------------- box/conf losses for batch b (tiny) --------------------
    const int b = blockIdx.x - NBLK;
    float s0=0.f, s1=0.f, s2=0.f, s3=0.f, s4=0.f;
    for (int i = tid; i < MM*NPTS; i += NTHR){
      int m  = i / NPTS;
      int pt = i % NPTS;
      const float* tbm = tboxes + ((size_t)b*MM + m)*5;
      float tconf = tbm[0];
      float nx1 = clipf(tbm[1] * (1.0f/512.0f), 0.f, 1.f);
      float ny1 = clipf(tbm[2] * (1.0f/512.0f), 0.f, 1.f);
      float nx2 = clipf(tbm[3] * (1.0f/512.0f), 0.f, 1.f);
      float ny2 = clipf(tbm[4] * (1.0f/512.0f), 0.f, 1.f);
      int x1p = min(max((int)(nx1 * 512.0f), 0), WW-1);
      int y1p = min(max((int)(ny1 * 512.0f), 0), HH-1);
      int x2p = min(max((int)(nx2 * 512.0f), 0), WW-1);
      int y2p = min(max((int)(ny2 * 512.0f), 0), HH-1);
      int cy = (y1p + y2p) >> 1;
      int cx = (x1p + x2p) >> 1;

      int yy, xx;
      switch (pt){
        case 0: yy = cy;  xx = cx;  break;
        case 1: yy = y1p; xx = x1p; break;
        case 2: yy = y1p; xx = x2p; break;
        case 3: yy = y2p; xx = x1p; break;
        default:yy = y2p; xx = x2p; break;
      }

      size_t hw  = (size_t)HH*WW;
      size_t off = (size_t)yy*WW + xx;
      const float* bb = bbox + (size_t)b*4*hw;
      float c0 = bb[off];
      float c1 = bb[hw   + off];
      float c2 = bb[2*hw + off];
      float c3 = bb[3*hw + off];
      float cp = conf[(size_t)b*hw + off];

      float px1 = clipf(c0, 0.00f, 0.99f);
      float py1 = clipf(c1, 0.00f, 0.99f);
      float px2 = clipf(c2, 0.01f, 1.00f);
      float py2 = clipf(c3, 0.01f, 1.00f);
      float bx1 = fminf(px1, px2), bx2 = fmaxf(px1, px2);
      float by1 = fminf(py1, py2), by2 = fmaxf(py1, py2);

      float pa = (bx2 - bx1) * (by2 - by1);
      float ta = (nx2 - nx1) * (ny2 - ny1);
      float ix1 = fmaxf(bx1, nx1), iy1 = fmaxf(by1, ny1);
      float ix2 = fminf(bx2, nx2), iy2 = fminf(by2, ny2);
      float inter = fmaxf(ix2 - ix1, 0.f) * fmaxf(iy2 - iy1, 0.f);
      float uni = pa + ta - inter;
      float iou = inter / (uni + 1e-6f);
      float ex1 = fminf(bx1, nx1), ey1 = fminf(by1, ny1);
      float ex2 = fmaxf(bx2, nx2), ey2 = fmaxf(by2, ny2);
      float enc = (ex2 - ex1) * (ey2 - ey1);
      float giou = iou - (enc - uni) / (enc + 1e-6f);

      float iou_pt  = -__logf(iou + 1e-6f);
      float giou_pt = 1.0f - giou;
      float l1_pt   = 0.25f * (sl1(bx1-nx1) + sl1(by1-ny1) + sl1(bx2-nx2) + sl1(by2-ny2));
      float bce     = -(tconf*__logf(cp) + (1.0f - tconf)*__logf(1.0f - cp));

      float mk = (float)bmask[b*MM + m];
      s0 = fmaf(iou_pt,  mk, s0);
      s1 = fmaf(l1_pt,   mk, s1);
      s2 = fmaf(giou_pt, mk, s2);
      s3 = fmaf(bce,     mk, s3);
      s4 += mk;
    }
    s0 = wredf(s0); s1 = wredf(s1); s2 = wredf(s2); s3 = wredf(s3); s4 = wredf(s4);
    __shared__ float shb[5][NTHR/32];
    if (l == 0){ shb[0][w]=s0; shb[1][w]=s1; shb[2][w]=s2; shb[3][w]=s3; shb[4][w]=s4; }
    __syncthreads();
    if (tid == 0){
      float a0=0,a1=0,a2=0,a3=0,a4=0;
      #pragma unroll
      for (int i = 0; i < NTHR/32; i++){
        a0+=shb[0][i]; a1+=shb[1][i]; a2+=shb[2][i]; a3+=shb[3][i]; a4+=shb[4][i];
      }
      float cnt = fmaxf(a4, 1.0f);
      g_box[b*3+0] = 0.5f*(a0/cnt) + 0.3f*(a1/cnt) + 0.2f*(a2/cnt);
      g_box[b*3+1] = a3/cnt;
      g_box[b*3+2] = (a4 > 0.f) ? 1.0f : 0.0f;
    }
  }

  // ------- last-block combine. ONLY tid 0 fences + bumps the counter -------
  __shared__ bool isLast;
  if (tid == 0){
    __threadfence();                       // release g_part/g_box (written by tid 0)
    unsigned int v = atomicAdd(&g_count, 1u);
    isLast = (v == (unsigned int)(GRID - 1));
    if (isLast) __threadfence();           // acquire before reading others' results
  }
  __syncthreads();
  if (!isLast) return;

  double s0=0.0, s1=0.0, s2=0.0, s3=0.0;
  for (int i = tid; i < NBLK; i += NTHR){
    s0 += (double)g_part[i*4+0];
    s1 += (double)g_part[i*4+1];
    s2 += (double)g_part[i*4+2];
    s3 += (double)g_part[i*4+3];
  }
  s0 = wredd(s0); s1 = wredd(s1); s2 = wredd(s2); s3 = wredd(s3);
  __shared__ double shd[4][NTHR/32];
  if (l == 0){ shd[0][w]=s0; shd[1][w]=s1; shd[2][w]=s2; shd[3][w]=s3; }
  __syncthreads();
  if (tid == 0){
    double Sb=0, Spt=0, Sp=0, St=0;
    #pragma unroll
    for (int i = 0; i < NTHR/32; i++){ Sb+=shd[0][i]; Spt+=shd[1][i]; Sp+=shd[2][i]; St+=shd[3][i]; }
    float bce_mean = (float)(Sb / (double)NTOT);
    float dice = (float)((2.0*Spt + 1e-5) / (Sp + St + 1e-5));
    float text_loss = 0.5f*bce_mean + 0.5f*(1.0f - dice);

    float nvalid = 0.f, sc = 0.f, scf = 0.f;
    #pragma unroll
    for (int b = 0; b < BQ; b++){
      float v = g_box[b*3+2];
      nvalid += v;
      sc  += g_box[b*3+0] * v;
      scf += g_box[b*3+1] * v;
    }
    nvalid = fmaxf(nvalid, 1.0f);
    out[0] = text_loss + 20.0f*(sc/nvalid) + 0.5f*(scf/nvalid);
    g_count = 0;   // reset for next graph replay
  }
}

extern "C" void kernel_launch(void* const* d_in, const int* in_sizes, int n_in,
                              void* d_out, int out_size){
  const float* text_map        = (const float*)d_in[0];
  const float* confidence      = (const float*)d_in[1];
  const float* bbox_coords     = (const float*)d_in[2];
  const float* target_text_map = (const float*)d_in[3];
  const float* target_boxes    = (const float*)d_in[4];
  const int*   box_mask        = (const int*)  d_in[5];

  fused_kernel<<<GRID, NTHR>>>((const float4*)text_map, (const float4*)target_text_map,
                               bbox_coords, confidence, target_boxes, box_mask,
                               (float*)d_out);
}

// round 5
// speedup vs baseline: 1.4289x; 1.2737x over previous
#include <cuda_runtime.h>
#include <cuda_bf16.h>

#define BQ  16
#define HH  512
#define WW  512
#define MM  64
#define NPTS 5
#define NTOT (BQ*HH*WW)      // 4194304
#define TBLK 512             // text blocks
#define NTHR 256
#define GRID (BQ + TBLK)     // 528 blocks -> single wave

// Scratch (no allocation allowed)
__device__ float g_part[TBLK*4];        // [block][bce, p*t, p, t]
__device__ float g_box[BQ*3];           // [b][combined, conf, valid]
__device__ unsigned int g_count;        // zero-initialized at module load

__device__ __forceinline__ float wredf(float v){
  #pragma unroll
  for (int o = 16; o > 0; o >>= 1) v += __shfl_xor_sync(0xffffffffu, v, o);
  return v;
}
__device__ __forceinline__ double wredd(double v){
  #pragma unroll
  for (int o = 16; o > 0; o >>= 1) v += __shfl_xor_sync(0xffffffffu, v, o);
  return v;
}
__device__ __forceinline__ float clipf(float x, float lo, float hi){
  return fminf(fmaxf(x, lo), hi);
}
__device__ __forceinline__ float sl1(float d){
  d = fabsf(d);
  return (d < 1.0f) ? 0.5f*d*d : d - 0.5f;
}

__device__ __forceinline__ void acc4(float4 pv, float4 tv,
                                     float& sb, float& spt, float& sp, float& st){
  float pa[4] = {pv.x, pv.y, pv.z, pv.w};
  float ta[4] = {tv.x, tv.y, tv.z, tv.w};
  #pragma unroll
  for (int c = 0; c < 4; c++){
    float pp = pa[c], tt = ta[c];
    // t is exactly 0 or 1
    sb  -= __logf(tt > 0.5f ? pp : 1.0f - pp);
    spt  = fmaf(pp, tt, spt);
    sp  += pp;
    st  += tt;
  }
}

__global__ void __launch_bounds__(NTHR)
fused_kernel(const float4* __restrict__ p4,        // text_map
             const float4* __restrict__ t4,        // target_text_map
             const float*  __restrict__ bbox,      // [B,4,H,W]
             const float*  __restrict__ conf,      // [B,1,H,W]
             const float*  __restrict__ tboxes,    // [B,M,5]
             const int*    __restrict__ bmask,     // [B,M]
             float*        __restrict__ out){
  const int tid = threadIdx.x;
  const int w = tid >> 5, l = tid & 31;

  if (blockIdx.x >= BQ){
    // ------------- text map BCE + dice partial sums (HBM-bound) -------------
    const int tb   = blockIdx.x - BQ;             // 0..TBLK-1
    const int base = tb * NTHR + tid;
    const int S    = TBLK * NTHR;                 // 131072; n4 = 8*S
    float sb = 0.f, spt = 0.f, sp = 0.f, st = 0.f;
    #pragma unroll 1
    for (int k = 0; k < 4; k++){
      int i0 = base + (2*k  )*S;
      int i1 = base + (2*k+1)*S;
      float4 a0 = p4[i0];
      float4 b0 = t4[i0];
      float4 a1 = p4[i1];
      float4 b1 = t4[i1];
      acc4(a0, b0, sb, spt, sp, st);
      acc4(a1, b1, sb, spt, sp, st);
    }
    sb = wredf(sb); spt = wredf(spt); sp = wredf(sp); st = wredf(st);
    __shared__ float sh[4][NTHR/32];
    if (l == 0){ sh[0][w]=sb; sh[1][w]=spt; sh[2][w]=sp; sh[3][w]=st; }
    __syncthreads();
    if (tid == 0){
      float a=0.f,b=0.f,c=0.f,d=0.f;
      #pragma unroll
      for (int i = 0; i < NTHR/32; i++){ a+=sh[0][i]; b+=sh[1][i]; c+=sh[2][i]; d+=sh[3][i]; }
      g_part[tb*4+0]=a; g_part[tb*4+1]=b;
      g_part[tb*4+2]=c; g_part[tb*4+3]=d;
    }
  } else {
    // -------- box/conf losses for batch b (scheduled FIRST to overlap) ------
    const int b = blockIdx.x;
    float s0=0.f, s1=0.f, s2=0.f, s3=0.f, s4=0.f;
    for (int i = tid; i < MM*NPTS; i += NTHR){
      int m  = i / NPTS;
      int pt = i % NPTS;
      const float* tbm = tboxes + ((size_t)b*MM + m)*5;
      float tconf = tbm[0];
      float nx1 = clipf(tbm[1] * (1.0f/512.0f), 0.f, 1.f);
      float ny1 = clipf(tbm[2] * (1.0f/512.0f), 0.f, 1.f);
      float nx2 = clipf(tbm[3] * (1.0f/512.0f), 0.f, 1.f);
      float ny2 = clipf(tbm[4] * (1.0f/512.0f), 0.f, 1.f);
      int x1p = min(max((int)(nx1 * 512.0f), 0), WW-1);
      int y1p = min(max((int)(ny1 * 512.0f), 0), HH-1);
      int x2p = min(max((int)(nx2 * 512.0f), 0), WW-1);
      int y2p = min(max((int)(ny2 * 512.0f), 0), HH-1);
      int cy = (y1p + y2p) >> 1;
      int cx = (x1p + x2p) >> 1;

      int yy, xx;
      switch (pt){
        case 0: yy = cy;  xx = cx;  break;
        case 1: yy = y1p; xx = x1p; break;
        case 2: yy = y1p; xx = x2p; break;
        case 3: yy = y2p; xx = x1p; break;
        default:yy = y2p; xx = x2p; break;
      }

      size_t hw  = (size_t)HH*WW;
      size_t off = (size_t)yy*WW + xx;
      const float* bb = bbox + (size_t)b*4*hw;
      float c0 = bb[off];
      float c1 = bb[hw   + off];
      float c2 = bb[2*hw + off];
      float c3 = bb[3*hw + off];
      float cp = conf[(size_t)b*hw + off];

      float px1 = clipf(c0, 0.00f, 0.99f);
      float py1 = clipf(c1, 0.00f, 0.99f);
      float px2 = clipf(c2, 0.01f, 1.00f);
      float py2 = clipf(c3, 0.01f, 1.00f);
      float bx1 = fminf(px1, px2), bx2 = fmaxf(px1, px2);
      float by1 = fminf(py1, py2), by2 = fmaxf(py1, py2);

      float pa = (bx2 - bx1) * (by2 - by1);
      float ta = (nx2 - nx1) * (ny2 - ny1);
      float ix1 = fmaxf(bx1, nx1), iy1 = fmaxf(by1, ny1);
      float ix2 = fminf(bx2, nx2), iy2 = fminf(by2, ny2);
      float inter = fmaxf(ix2 - ix1, 0.f) * fmaxf(iy2 - iy1, 0.f);
      float uni = pa + ta - inter;
      float iou = inter / (uni + 1e-6f);
      float ex1 = fminf(bx1, nx1), ey1 = fminf(by1, ny1);
      float ex2 = fmaxf(bx2, nx2), ey2 = fmaxf(by2, ny2);
      float enc = (ex2 - ex1) * (ey2 - ey1);
      float giou = iou - (enc - uni) / (enc + 1e-6f);

      float iou_pt  = -__logf(iou + 1e-6f);
      float giou_pt = 1.0f - giou;
      float l1_pt   = 0.25f * (sl1(bx1-nx1) + sl1(by1-ny1) + sl1(bx2-nx2) + sl1(by2-ny2));
      float bce     = -(tconf*__logf(cp) + (1.0f - tconf)*__logf(1.0f - cp));

      float mk = (float)bmask[b*MM + m];
      s0 = fmaf(iou_pt,  mk, s0);
      s1 = fmaf(l1_pt,   mk, s1);
      s2 = fmaf(giou_pt, mk, s2);
      s3 = fmaf(bce,     mk, s3);
      s4 += mk;
    }
    s0 = wredf(s0); s1 = wredf(s1); s2 = wredf(s2); s3 = wredf(s3); s4 = wredf(s4);
    __shared__ float shb[5][NTHR/32];
    if (l == 0){ shb[0][w]=s0; shb[1][w]=s1; shb[2][w]=s2; shb[3][w]=s3; shb[4][w]=s4; }
    __syncthreads();
    if (tid == 0){
      float a0=0,a1=0,a2=0,a3=0,a4=0;
      #pragma unroll
      for (int i = 0; i < NTHR/32; i++){
        a0+=shb[0][i]; a1+=shb[1][i]; a2+=shb[2][i]; a3+=shb[3][i]; a4+=shb[4][i];
      }
      float cnt = fmaxf(a4, 1.0f);
      g_box[b*3+0] = 0.5f*(a0/cnt) + 0.3f*(a1/cnt) + 0.2f*(a2/cnt);
      g_box[b*3+1] = a3/cnt;
      g_box[b*3+2] = (a4 > 0.f) ? 1.0f : 0.0f;
    }
  }

  // ------- last-block combine. ONLY tid 0 fences + bumps the counter -------
  __shared__ bool isLast;
  if (tid == 0){
    __threadfence();                       // release g_part/g_box (written by tid 0)
    unsigned int v = atomicAdd(&g_count, 1u);
    isLast = (v == (unsigned int)(GRID - 1));
    if (isLast) __threadfence();           // acquire before reading others' results
  }
  __syncthreads();
  if (!isLast) return;

  double s0=0.0, s1=0.0, s2=0.0, s3=0.0;
  for (int i = tid; i < TBLK; i += NTHR){
    s0 += (double)g_part[i*4+0];
    s1 += (double)g_part[i*4+1];
    s2 += (double)g_part[i*4+2];
    s3 += (double)g_part[i*4+3];
  }
  s0 = wredd(s0); s1 = wredd(s1); s2 = wredd(s2); s3 = wredd(s3);
  __shared__ double shd[4][NTHR/32];
  if (l == 0){ shd[0][w]=s0; shd[1][w]=s1; shd[2][w]=s2; shd[3][w]=s3; }
  __syncthreads();
  if (tid == 0){
    double Sb=0, Spt=0, Sp=0, St=0;
    #pragma unroll
    for (int i = 0; i < NTHR/32; i++){ Sb+=shd[0][i]; Spt+=shd[1][i]; Sp+=shd[2][i]; St+=shd[3][i]; }
    float bce_mean = (float)(Sb / (double)NTOT);
    float dice = (float)((2.0*Spt + 1e-5) / (Sp + St + 1e-5));
    float text_loss = 0.5f*bce_mean + 0.5f*(1.0f - dice);

    float nvalid = 0.f, sc = 0.f, scf = 0.f;
    #pragma unroll
    for (int b = 0; b < BQ; b++){
      float v = g_box[b*3+2];
      nvalid += v;
      sc  += g_box[b*3+0] * v;
      scf += g_box[b*3+1] * v;
    }
    nvalid = fmaxf(nvalid, 1.0f);
    out[0] = text_loss + 20.0f*(sc/nvalid) + 0.5f*(scf/nvalid);
    g_count = 0;   // reset for next graph replay
  }
}

extern "C" void kernel_launch(void* const* d_in, const int* in_sizes, int n_in,
                              void* d_out, int out_size){
  const float* text_map        = (const float*)d_in[0];
  const float* confidence      = (const float*)d_in[1];
  const float* bbox_coords     = (const float*)d_in[2];
  const float* target_text_map = (const float*)d_in[3];
  const float* target_boxes    = (const float*)d_in[4];
  const int*   box_mask        = (const int*)  d_in[5];

  fused_kernel<<<GRID, NTHR>>>((const float4*)text_map, (const float4*)target_text_map,
                               bbox_coords, confidence, target_boxes, box_mask,
                               (float*)d_out);
}